// round 6
// baseline (speedup 1.0000x reference)
#include <cuda_runtime.h>
#include <cstdint>

#define BS 4
#define SQ 1024
#define CH 64
#define UN 32
#define TSPAN 72   // 8 query rows + 64 window
#define GRID (BS * 128)

__device__ float g_k[BS * SQ * UN];
__device__ unsigned g_count = 0;
__device__ volatile unsigned g_sense = 0;

__device__ __forceinline__ float htanh(float x) {
    float y;
    asm("tanh.approx.f32 %0, %1;" : "=f"(y) : "f"(x));
    return y;
}

// ---------------------------------------------------------------------------
// Single persistent kernel. grid = 512 blocks x 512 threads, all resident
// (launch_bounds(512,4): regs<=32, smem 40.9KB*4 <= 228KB, 512 <= 148*4).
// Phase 1: q for own 8 rows -> qs (smem, block-local only); k -> g_k.
// Device-wide sense-reversing barrier (replay-safe).
// Phase 2: windowed additive attention (as before) + xts XOR swizzle.
// ---------------------------------------------------------------------------
__global__ __launch_bounds__(512, 4) void fused_kernel(
    const float* __restrict__ x,
    const float* __restrict__ Wt,
    const float* __restrict__ Wx,
    const float* __restrict__ bh,
    const float* __restrict__ wa,
    float* __restrict__ vout,
    float* __restrict__ aout)
{
    // phase1: wts[32][76] + wxs[32][76] = 4864 floats.  phase2: xts[72][68]
    __shared__ __align__(16) float regionA[TSPAN * 68];
    // phase1: xs[8][68] = 544 floats.                   phase2: vs[32][68]
    __shared__ __align__(16) float regionB[32 * 68];
    __shared__ __align__(16) float qs[8 * 32];    // [r][u] (written phase 1)
    __shared__ __align__(16) float a_s[8 * 64];   // [r][j]
    __shared__ __align__(16) float was[UN];
    __shared__ float sumbuf[8][2];
    __shared__ float ks_t[UN * 73];               // [u][ti]

    int b = blockIdx.x >> 7;
    int s0 = (blockIdx.x & 127) << 3;
    int tid = threadIdx.x;

    // ================= phase 1: q,k for own 8 rows ==================
    {
        float* wts = regionA;             // [u][c], stride 76 (bank-staggered)
        float* wxs = regionA + UN * 76;
        float* xs  = regionB;             // [s][c], stride 68

        const float4* wt4 = (const float4*)Wt;
        const float4* wx4 = (const float4*)Wx;
        int u = tid >> 4, g = tid & 15;   // 512 threads = 32u x 16 groups
        *(float4*)&wts[u * 76 + g * 4] = wt4[tid];
        *(float4*)&wxs[u * 76 + g * 4] = wx4[tid];
        int c = tid >> 3, s = tid & 7;    // 512 = 64c x 8s
        xs[s * 68 + c] = x[(size_t)b * CH * SQ + c * SQ + s0 + s];
        __syncthreads();

        int ss = (tid >> 5) & 7;          // warps 0-7: q rows; warps 8-15: k rows
        int uu = tid & 31;
        const float* wrow = (tid < 256) ? &wts[uu * 76] : &wxs[uu * 76];
        float a0 = 0.f, a1 = 0.f, a2 = 0.f, a3 = 0.f;
#pragma unroll
        for (int it = 0; it < 16; it++) {
            float4 x4 = *(const float4*)&xs[ss * 68 + it * 4];
            float4 w4 = *(const float4*)&wrow[it * 4];
            a0 = fmaf(x4.x, w4.x, a0); a1 = fmaf(x4.y, w4.y, a1);
            a2 = fmaf(x4.z, w4.z, a2); a3 = fmaf(x4.w, w4.w, a3);
        }
        float res = (a0 + a1) + (a2 + a3);
        if (tid < 256) {
            qs[ss * 32 + uu] = res;                                  // block-local
        } else {
            g_k[((size_t)b * SQ + s0 + ss) * UN + uu] = res + bh[uu];  // bh folded
            __threadfence();   // make k visible before barrier arrival
        }
    }
    __syncthreads();

    // ================= device-wide barrier (sense-reversing) ========
    if (tid == 0) {
        unsigned sns = g_sense;
        if (atomicAdd(&g_count, 1u) == (unsigned)(GRID - 1)) {
            g_count = 0;
            __threadfence();
            g_sense = sns ^ 1u;
        } else {
            while (g_sense == sns) { }
        }
    }
    __syncthreads();

    // ================= phase 2: windowed attention ==================
    int w2 = tid >> 5;          // 0..15
    int r = w2 >> 1;            // query row in block
    int h = w2 & 1;             // window half
    int ln = tid & 31;
    int tlo = s0 - 32;
    float* xts = regionA;       // [ti][c-swizzled], stride 68
    float* vs  = regionB;       // [(r*4+jseg)][c], stride 68

    if (tid < UN) was[tid] = wa[tid];

    // k halo, transposed (pad 73: conflict-free scatter + read)
    for (int lin = tid; lin < TSPAN * UN; lin += 512) {
        int u = lin & 31, ti = lin >> 5;
        int t = tlo + ti;
        int tc = min(max(t, 0), SQ - 1);
        ks_t[u * 73 + ti] = g_k[((size_t)b * SQ + tc) * UN + u];
    }

    // x halo: LDG coalesced, STS bank-conflict-free via 16B XOR swizzle
    {
        int cc = tid >> 3, t8 = tid & 7;
        int gbase = cc >> 2, clo = cc & 3;
        const float* xb = x + (size_t)b * CH * SQ + cc * SQ;
#pragma unroll
        for (int p = 0; p < 9; p++) {
            int ti = p * 8 + t8;
            int t = tlo + ti;
            int tc = min(max(t, 0), SQ - 1);
            int csw = ((gbase ^ t8) << 2) | clo;   // ti&7 == t8
            xts[ti * 68 + csw] = xb[tc];
        }
    }
    __syncthreads();

    int s = s0 + r;
    int j = h * 32 + ln;
    int t = s - 32 + j;
    bool valid = (t >= 0) && (t < SQ);
    int ti = r + j;             // <= 70

    const float4* qp = (const float4*)&qs[r * 32];
    const float4* wap = (const float4*)was;
    float acc = 0.f;
#pragma unroll
    for (int g = 0; g < 8; g++) {
        float4 q4 = qp[g];
        float4 w4 = wap[g];
        float k0 = ks_t[(g * 4 + 0) * 73 + ti];
        float k1 = ks_t[(g * 4 + 1) * 73 + ti];
        float k2 = ks_t[(g * 4 + 2) * 73 + ti];
        float k3 = ks_t[(g * 4 + 3) * 73 + ti];
        acc = fmaf(w4.x, htanh(q4.x + k0), acc);
        acc = fmaf(w4.y, htanh(q4.y + k1), acc);
        acc = fmaf(w4.z, htanh(q4.z + k2), acc);
        acc = fmaf(w4.w, htanh(q4.w + k3), acc);
    }

    // softmax without max-shift (scores bounded by sum|wa|; shift cancels
    // in softmax except through eps: rel err <= ~1.3e-5)
    float e = valid ? __expf(acc) : 0.f;
    float sm = e;
#pragma unroll
    for (int o = 16; o > 0; o >>= 1) sm += __shfl_xor_sync(0xffffffffu, sm, o);
    if (ln == 0) sumbuf[r][h] = sm;
    __syncthreads();
    float inv = __fdividef(1.f, sumbuf[r][0] + sumbuf[r][1] + 1e-7f);
    float a = e * inv;
    a_s[(r << 6) + j] = a;
    __syncthreads();   // a_s complete (read cross-warp below)

    // --- a row write: warp-uniform branch; window hits <=2 of 8 segments ---
    float4 z4 = make_float4(0.f, 0.f, 0.f, 0.f);
    float4* arow = (float4*)(aout + (((size_t)b * SQ + s) << 10));
#pragma unroll
    for (int i = 0; i < 4; i++) {
        int col0 = (h << 9) + (i << 7);   // warp-uniform segment start
        int col = col0 + (ln << 2);
        if (col0 > s + 31 || col0 + 127 < s - 32) {
            arow[col >> 2] = z4;
        } else {
            int jw = col - s + 32;
            float4 val;
            val.x = ((unsigned)(jw + 0) < 64u) ? a_s[(r << 6) + jw + 0] : 0.f;
            val.y = ((unsigned)(jw + 1) < 64u) ? a_s[(r << 6) + jw + 1] : 0.f;
            val.z = ((unsigned)(jw + 2) < 64u) ? a_s[(r << 6) + jw + 2] : 0.f;
            val.w = ((unsigned)(jw + 3) < 64u) ? a_s[(r << 6) + jw + 3] : 0.f;
            arow[col >> 2] = val;
        }
    }

    // --- v pass: per row, 64 threads = 16 channel-groups x 4 j-segments ---
    {
        int q64 = tid & 63;
        int cgrp = q64 & 15;      // 4 channels
        int jseg = q64 >> 4;      // 16 j each
        float4 vacc = z4;
#pragma unroll
        for (int it = 0; it < 16; it++) {
            int jj = jseg * 16 + it;
            int row = r + jj;
            float av = a_s[(r << 6) + jj];
            float4 x4 = *(const float4*)&xts[row * 68 + ((cgrp ^ (row & 7)) << 2)];
            vacc.x = fmaf(av, x4.x, vacc.x);
            vacc.y = fmaf(av, x4.y, vacc.y);
            vacc.z = fmaf(av, x4.z, vacc.z);
            vacc.w = fmaf(av, x4.w, vacc.w);
        }
        *(float4*)&vs[((r << 2) + jseg) * 68 + (cgrp << 2)] = vacc;
    }
    __syncthreads();

    // combine 4 j-segment partials + coalesced transposed v write
    {
        int c = tid >> 3, i = tid & 7;
        float vsum = (vs[(i * 4 + 0) * 68 + c] + vs[(i * 4 + 1) * 68 + c]) +
                     (vs[(i * 4 + 2) * 68 + c] + vs[(i * 4 + 3) * 68 + c]);
        vout[(size_t)b * CH * SQ + c * SQ + s0 + i] = vsum;
    }
}

extern "C" void kernel_launch(void* const* d_in, const int* in_sizes, int n_in,
                              void* d_out, int out_size) {
    (void)in_sizes; (void)n_in; (void)out_size;
    const float* x  = (const float*)d_in[0];
    const float* Wt = (const float*)d_in[1];
    const float* Wx = (const float*)d_in[2];
    const float* Wa = (const float*)d_in[3];
    // d_in[4] = Wa_b: cancels exactly in the softmax, unused
    const float* bh = (const float*)d_in[5];

    float* vout = (float*)d_out;                     // (B, C, S)
    float* aout = vout + (size_t)BS * CH * SQ;       // (B, S, S)

    fused_kernel<<<GRID, 512>>>(x, Wt, Wx, bh, Wa, vout, aout);
}

// round 7
// speedup vs baseline: 1.0565x; 1.0565x over previous
#include <cuda_runtime.h>
#include <cstdint>

#define BS 4
#define SQ 1024
#define CH 64
#define UN 32
#define TSPAN 72   // 8 query rows + 64 window
#define GRID (BS * 128)

__device__ float g_k[BS * SQ * UN];
__device__ unsigned g_flag[GRID];   // monotonic per-block launch counters

__device__ __forceinline__ float htanh(float x) {
    float y;
    asm("tanh.approx.f32 %0, %1;" : "=f"(y) : "f"(x));
    return y;
}

// ---------------------------------------------------------------------------
// Single fused kernel, NEIGHBOR-ONLY sync (no device-wide barrier).
// grid = 512 blocks x 512 threads, all resident (regs<=32, smem ~41KB x4).
// Phase 1: q (own 8 rows) -> smem qs; k (own 8 rows) -> g_k; flag++.
// Then: fill xts while warp 0 lanes spin on <=9 neighbor flags (b, sblk+-4).
// Phase 2: windowed additive attention; softmax with single barrier
// (a_s holds unnormalized e; inv folded into a-write and v scale).
// ---------------------------------------------------------------------------
__global__ __launch_bounds__(512, 4) void fused_kernel(
    const float* __restrict__ x,
    const float* __restrict__ Wt,
    const float* __restrict__ Wx,
    const float* __restrict__ bh,
    const float* __restrict__ wa,
    float* __restrict__ vout,
    float* __restrict__ aout)
{
    // phase1: wts[32][76] + wxs[32][76] = 4864 floats.  phase2: xts[72][68]
    __shared__ __align__(16) float regionA[TSPAN * 68];
    // phase1: xs[8][68] = 544 floats.                   phase2: vs[32][68]
    __shared__ __align__(16) float regionB[32 * 68];
    __shared__ __align__(16) float qs[8 * 32];    // [r][u] (written phase 1)
    __shared__ __align__(16) float a_s[8 * 64];   // [r][j] (unnormalized e)
    __shared__ __align__(16) float was[UN];
    __shared__ float sumbuf[8][2];
    __shared__ float ks_t[UN * 73];               // [u][ti]
    __shared__ unsigned smyval;

    int b = blockIdx.x >> 7;
    int sblk = blockIdx.x & 127;
    int s0 = sblk << 3;
    int tid = threadIdx.x;

    // ================= phase 1: q,k for own 8 rows ==================
    {
        float* wts = regionA;             // [u][c], stride 76
        float* wxs = regionA + UN * 76;
        float* xs  = regionB;             // [s][c], stride 68

        const float4* wt4 = (const float4*)Wt;
        const float4* wx4 = (const float4*)Wx;
        int u = tid >> 4, g = tid & 15;   // 512 threads = 32u x 16 groups
        *(float4*)&wts[u * 76 + g * 4] = wt4[tid];
        *(float4*)&wxs[u * 76 + g * 4] = wx4[tid];
        int c = tid >> 3, s = tid & 7;    // 512 = 64c x 8s
        xs[s * 68 + c] = x[(size_t)b * CH * SQ + c * SQ + s0 + s];
        if (tid < UN) was[tid] = wa[tid];
        __syncthreads();                  // SYNC_A

        int ss = (tid >> 5) & 7;          // warps 0-7: q rows; warps 8-15: k rows
        int uu = tid & 31;
        const float* wrow = (tid < 256) ? &wts[uu * 76] : &wxs[uu * 76];
        float a0 = 0.f, a1 = 0.f, a2 = 0.f, a3 = 0.f;
#pragma unroll
        for (int it = 0; it < 16; it++) {
            float4 x4 = *(const float4*)&xs[ss * 68 + it * 4];
            float4 w4 = *(const float4*)&wrow[it * 4];
            a0 = fmaf(x4.x, w4.x, a0); a1 = fmaf(x4.y, w4.y, a1);
            a2 = fmaf(x4.z, w4.z, a2); a3 = fmaf(x4.w, w4.w, a3);
        }
        float res = (a0 + a1) + (a2 + a3);
        if (tid < 256) {
            qs[ss * 32 + uu] = res;                                   // block-local
        } else {
            g_k[((size_t)b * SQ + s0 + ss) * UN + uu] = res + bh[uu]; // bh folded
        }
    }
    __syncthreads();                      // SYNC_B: k stores done, regions free

    // release own flag (cumulative fence orders all block's k writes)
    if (tid == 0) {
        __threadfence();
        smyval = atomicAdd(&g_flag[blockIdx.x], 1u) + 1u;
    }

    int tlo = s0 - 32;
    float* xts = regionA;       // [ti][c-swizzled], stride 68
    float* vs  = regionB;

    // warp 0: spin on neighbor flags (overlapped with other warps' xts fill)
    if (tid < 32) {
        __syncwarp();           // smyval visible within warp 0
        int nlo = max(sblk - 4, 0);
        int nhi = min(sblk + 4, 127);
        if (tid <= nhi - nlo) {
            unsigned mv = smyval;
            volatile unsigned* f = (volatile unsigned*)&g_flag[(b << 7) + nlo + tid];
            while (*f < mv) { }
            __threadfence();    // acquire
        }
        __syncwarp();
    }

    // x halo: LDG coalesced, STS conflict-free via 16B XOR swizzle
    {
        int cc = tid >> 3, t8 = tid & 7;
        int gbase = cc >> 2, clo = cc & 3;
        const float* xb = x + (size_t)b * CH * SQ + cc * SQ;
#pragma unroll
        for (int p = 0; p < 9; p++) {
            int ti = p * 8 + t8;
            int t = tlo + ti;
            int tc = min(max(t, 0), SQ - 1);
            int csw = ((gbase ^ t8) << 2) | clo;   // ti&7 == t8
            xts[ti * 68 + csw] = xb[tc];
        }
    }
    __syncthreads();            // SYNC_C: xts done + neighbors' k visible

    // k halo, transposed (pad 73: conflict-free scatter + read)
    for (int lin = tid; lin < TSPAN * UN; lin += 512) {
        int u = lin & 31, ti = lin >> 5;
        int t = tlo + ti;
        int tc = min(max(t, 0), SQ - 1);
        ks_t[u * 73 + ti] = g_k[((size_t)b * SQ + tc) * UN + u];
    }
    __syncthreads();            // SYNC_D

    // ================= phase 2: scores + softmax ==================
    int w2 = tid >> 5;          // 0..15
    int r = w2 >> 1;            // query row in block
    int h = w2 & 1;             // window half
    int ln = tid & 31;

    int s = s0 + r;
    int j = h * 32 + ln;
    int t = s - 32 + j;
    bool valid = (t >= 0) && (t < SQ);
    int ti = r + j;             // <= 70

    const float4* qp = (const float4*)&qs[r * 32];
    const float4* wap = (const float4*)was;
    float acc = 0.f;
#pragma unroll
    for (int g = 0; g < 8; g++) {
        float4 q4 = qp[g];
        float4 w4 = wap[g];
        float k0 = ks_t[(g * 4 + 0) * 73 + ti];
        float k1 = ks_t[(g * 4 + 1) * 73 + ti];
        float k2 = ks_t[(g * 4 + 2) * 73 + ti];
        float k3 = ks_t[(g * 4 + 3) * 73 + ti];
        acc = fmaf(w4.x, htanh(q4.x + k0), acc);
        acc = fmaf(w4.y, htanh(q4.y + k1), acc);
        acc = fmaf(w4.z, htanh(q4.z + k2), acc);
        acc = fmaf(w4.w, htanh(q4.w + k3), acc);
    }

    // softmax without max-shift (scores bounded by sum|wa|; shift cancels
    // in softmax except through eps: rel err <= ~1.3e-5)
    float e = valid ? __expf(acc) : 0.f;
    float sm = e;
#pragma unroll
    for (int o = 16; o > 0; o >>= 1) sm += __shfl_xor_sync(0xffffffffu, sm, o);
    if (ln == 0) sumbuf[r][h] = sm;
    a_s[(r << 6) + j] = e;      // unnormalized
    __syncthreads();            // SYNC_E (single softmax barrier)

    float inv = __fdividef(1.f, sumbuf[r][0] + sumbuf[r][1] + 1e-7f);

    // --- a row write: warp-uniform branch; window hits <=2 of 8 segments ---
    float4 z4 = make_float4(0.f, 0.f, 0.f, 0.f);
    float4* arow = (float4*)(aout + (((size_t)b * SQ + s) << 10));
#pragma unroll
    for (int i = 0; i < 4; i++) {
        int col0 = (h << 9) + (i << 7);   // warp-uniform segment start
        int col = col0 + (ln << 2);
        if (col0 > s + 31 || col0 + 127 < s - 32) {
            arow[col >> 2] = z4;
        } else {
            int jw = col - s + 32;
            float4 val;
            val.x = ((unsigned)(jw + 0) < 64u) ? a_s[(r << 6) + jw + 0] * inv : 0.f;
            val.y = ((unsigned)(jw + 1) < 64u) ? a_s[(r << 6) + jw + 1] * inv : 0.f;
            val.z = ((unsigned)(jw + 2) < 64u) ? a_s[(r << 6) + jw + 2] * inv : 0.f;
            val.w = ((unsigned)(jw + 3) < 64u) ? a_s[(r << 6) + jw + 3] * inv : 0.f;
            arow[col >> 2] = val;
        }
    }

    // --- v pass: per row, 64 threads = 16 channel-groups x 4 j-segments ---
    {
        int q64 = tid & 63;
        int cgrp = q64 & 15;      // 4 channels
        int jseg = q64 >> 4;      // 16 j each
        float4 vacc = z4;
#pragma unroll
        for (int it = 0; it < 16; it++) {
            int jj = jseg * 16 + it;
            int row = r + jj;
            float av = a_s[(r << 6) + jj];
            float4 x4 = *(const float4*)&xts[row * 68 + ((cgrp ^ (row & 7)) << 2)];
            vacc.x = fmaf(av, x4.x, vacc.x);
            vacc.y = fmaf(av, x4.y, vacc.y);
            vacc.z = fmaf(av, x4.z, vacc.z);
            vacc.w = fmaf(av, x4.w, vacc.w);
        }
        vacc.x *= inv; vacc.y *= inv; vacc.z *= inv; vacc.w *= inv;
        *(float4*)&vs[((r << 2) + jseg) * 68 + (cgrp << 2)] = vacc;
    }
    __syncthreads();            // SYNC_F

    // combine 4 j-segment partials + coalesced transposed v write
    {
        int c = tid >> 3, i = tid & 7;
        float vsum = (vs[(i * 4 + 0) * 68 + c] + vs[(i * 4 + 1) * 68 + c]) +
                     (vs[(i * 4 + 2) * 68 + c] + vs[(i * 4 + 3) * 68 + c]);
        vout[(size_t)b * CH * SQ + c * SQ + s0 + i] = vsum;
    }
}

extern "C" void kernel_launch(void* const* d_in, const int* in_sizes, int n_in,
                              void* d_out, int out_size) {
    (void)in_sizes; (void)n_in; (void)out_size;
    const float* x  = (const float*)d_in[0];
    const float* Wt = (const float*)d_in[1];
    const float* Wx = (const float*)d_in[2];
    const float* Wa = (const float*)d_in[3];
    // d_in[4] = Wa_b: cancels exactly in the softmax, unused
    const float* bh = (const float*)d_in[5];

    float* vout = (float*)d_out;                     // (B, C, S)
    float* aout = vout + (size_t)BS * CH * SQ;       // (B, S, S)

    fused_kernel<<<GRID, 512>>>(x, Wt, Wx, bh, Wa, vout, aout);
}